// round 1
// baseline (speedup 1.0000x reference)
#include <cuda_runtime.h>
#include <cstdint>
#include <math.h>

#define Hh 384
#define Ww 384
#define HWsz 147456
#define NB 4

// ---------------- static device scratch (no allocations allowed) ----------------
static __device__ float g_det1[(size_t)NB * 64 * HWsz];   // det conv1 out (b0) / branch t64 (all b)
static __device__ float g_det2[(size_t)128 * HWsz];       // det conv2 out (batch 0 only)
static __device__ float g_pool[256];                      // det conv3 global-sum (batch 0)
static __device__ int   g_sel[1];                         // branch selection
static __device__ float g_xb[(size_t)NB * 32 * HWsz];     // branch output
static __device__ float g_qkv_pre[(size_t)NB * 96 * HWsz];
static __device__ float g_qkv[(size_t)NB * 96 * HWsz];
static __device__ float g_ssq[256];                       // [qk][b][32] sum of squares
static __device__ float g_S[512];                         // [b][h][4][4] gram
static __device__ float g_attn[512];                      // softmaxed attention
static __device__ float g_ff[(size_t)NB * 32 * HWsz];     // after ff1+gelu

__device__ __forceinline__ float gelu_exact(float x) {
    return 0.5f * x * (1.0f + erff(x * 0.70710678118654752f));
}

// ---------------- generic 3x3 conv, pad=1 ----------------
// block: 32x4 threads; tile: 32W x 4H x 16 oc; each thread: 4 rows x 4 ocs.
// POOL variant: fuses bias+relu+global spatial sum (atomicAdd into out[oc]).
template<int CIN, bool POOL>
__global__ void __launch_bounds__(128) conv3x3_k(
    const float* __restrict__ in, const float* __restrict__ w,
    const float* __restrict__ bias, float* __restrict__ out,
    int Cout, int doRelu, const int* selp, int selv)
{
    if (selp && __ldg(selp) != selv) return;
    const int tx = threadIdx.x;
    const int ty = threadIdx.y;
    const int x0 = blockIdx.x * 32;
    const int y0 = blockIdx.y * 4;
    const int ocGroups = Cout >> 4;
    const int b   = blockIdx.z / ocGroups;
    const int ocb = (blockIdx.z % ocGroups) << 4;

    __shared__ float s_in[4][6][34];
    __shared__ float s_w[16][4][9];

    const float* inb = in + (size_t)b * CIN * HWsz;
    float acc[4][4];
#pragma unroll
    for (int r = 0; r < 4; r++)
#pragma unroll
        for (int o = 0; o < 4; o++) acc[r][o] = 0.f;

    const int tid = ty * 32 + tx;
    for (int cin0 = 0; cin0 < CIN; cin0 += 4) {
        for (int idx = tid; idx < 4 * 6 * 34; idx += 128) {
            int cc  = idx / 204;
            int rem = idx - cc * 204;
            int r   = rem / 34;
            int col = rem - r * 34;
            int gr = y0 + r - 1;
            int gc = x0 + col - 1;
            float v = 0.f;
            if (gr >= 0 && gr < Hh && gc >= 0 && gc < Ww)
                v = inb[(size_t)(cin0 + cc) * HWsz + gr * Ww + gc];
            s_in[cc][r][col] = v;
        }
        for (int idx = tid; idx < 16 * 4 * 9; idx += 128) {
            int oc  = idx / 36;
            int rem = idx - oc * 36;
            int cc  = rem / 9;
            int k   = rem - cc * 9;
            s_w[oc][cc][k] = w[((size_t)(ocb + oc) * CIN + cin0 + cc) * 9 + k];
        }
        __syncthreads();
#pragma unroll
        for (int cc = 0; cc < 4; cc++) {
            float xin[6][3];
#pragma unroll
            for (int r = 0; r < 6; r++)
#pragma unroll
                for (int j = 0; j < 3; j++)
                    xin[r][j] = s_in[cc][r][tx + j];
#pragma unroll
            for (int o = 0; o < 4; o++) {
                float wv[9];
#pragma unroll
                for (int k = 0; k < 9; k++) wv[k] = s_w[ty * 4 + o][cc][k];
#pragma unroll
                for (int r = 0; r < 4; r++) {
                    float s = acc[r][o];
                    s = fmaf(wv[0], xin[r    ][0], s);
                    s = fmaf(wv[1], xin[r    ][1], s);
                    s = fmaf(wv[2], xin[r    ][2], s);
                    s = fmaf(wv[3], xin[r + 1][0], s);
                    s = fmaf(wv[4], xin[r + 1][1], s);
                    s = fmaf(wv[5], xin[r + 1][2], s);
                    s = fmaf(wv[6], xin[r + 2][0], s);
                    s = fmaf(wv[7], xin[r + 2][1], s);
                    s = fmaf(wv[8], xin[r + 2][2], s);
                    acc[r][o] = s;
                }
            }
        }
        __syncthreads();
    }

    if (!POOL) {
#pragma unroll
        for (int o = 0; o < 4; o++) {
            int oc = ocb + ty * 4 + o;
            float bv = bias ? bias[oc] : 0.f;
#pragma unroll
            for (int r = 0; r < 4; r++) {
                float v = acc[r][o] + bv;
                if (doRelu) v = fmaxf(v, 0.f);
                out[(size_t)(b * Cout + oc) * HWsz + (size_t)(y0 + r) * Ww + x0 + tx] = v;
            }
        }
    } else {
#pragma unroll
        for (int o = 0; o < 4; o++) {
            int oc = ocb + ty * 4 + o;
            float bv = bias[oc];
            float s = 0.f;
#pragma unroll
            for (int r = 0; r < 4; r++) s += fmaxf(acc[r][o] + bv, 0.f);
#pragma unroll
            for (int off = 16; off; off >>= 1)
                s += __shfl_down_sync(0xffffffffu, s, off);
            if (tx == 0) atomicAdd(&out[oc], s);
        }
    }
}

// ---------------- zero pool ----------------
__global__ void zero_pool_k() {
    if (threadIdx.x < 256) g_pool[threadIdx.x] = 0.f;
}

// ---------------- logits + argmax (batch 0 only) ----------------
__global__ void logits_k(const float* __restrict__ fcw, const float* __restrict__ fcb) {
    __shared__ float l[3];
    int t = threadIdx.x;
    if (t < 3) {
        float s = 0.f;
        const float inv = 1.0f / (float)HWsz;
        for (int k = 0; k < 256; k++)
            s = fmaf(fcw[t * 256 + k], g_pool[k] * inv, s);
        l[t] = s + fcb[t];
    }
    __syncthreads();
    if (t == 0) {
        int best = 0; float bv = l[0];
        if (l[1] > bv) { bv = l[1]; best = 1; }
        if (l[2] > bv) { bv = l[2]; best = 2; }
        g_sel[0] = best;
    }
}

// ---------------- rgb branch: xb = x (predicated sel==0) ----------------
__global__ void copy_rgb_k(const float* __restrict__ x) {
    if (__ldg(g_sel) != 0) return;
    size_t i = (size_t)blockIdx.x * blockDim.x + threadIdx.x;
    const float4* src = (const float4*)x;
    float4* dst = (float4*)g_xb;
    size_t n4 = (size_t)NB * 32 * HWsz / 4;
    if (i < n4) dst[i] = src[i];
}

// ---------------- fused channels-first LayerNorm + 1x1 pwconv (C=32 -> 96), 2 px/thread ----------------
__global__ void __launch_bounds__(128) ln_pw_k(
    const float* __restrict__ lnw, const float* __restrict__ lnb,
    const float* __restrict__ pww)
{
    __shared__ float s_w[96 * 32];
    __shared__ float s_lw[32], s_lb[32];
    int tid = threadIdx.x;
    for (int i = tid; i < 96 * 32; i += 128) s_w[i] = pww[i];
    if (tid < 32) { s_lw[tid] = lnw[tid]; s_lb[tid] = lnb[tid]; }
    __syncthreads();

    size_t pair = (size_t)blockIdx.x * 128 + tid;           // 0 .. NB*HW/2-1
    size_t gp = pair * 2;
    int b = (int)(gp / HWsz);
    int p = (int)(gp % HWsz);

    float a0[32], a1[32];
    float m0 = 0.f, m1 = 0.f;
#pragma unroll
    for (int c = 0; c < 32; c++) {
        float2 v = *(const float2*)&g_xb[(size_t)(b * 32 + c) * HWsz + p];
        a0[c] = v.x; a1[c] = v.y;
        m0 += v.x; m1 += v.y;
    }
    m0 *= (1.f / 32.f); m1 *= (1.f / 32.f);
    float v0 = 0.f, v1 = 0.f;
#pragma unroll
    for (int c = 0; c < 32; c++) {
        float d0 = a0[c] - m0, d1 = a1[c] - m1;
        v0 = fmaf(d0, d0, v0); v1 = fmaf(d1, d1, v1);
    }
    float r0 = rsqrtf(v0 * (1.f / 32.f) + 1e-6f);
    float r1 = rsqrtf(v1 * (1.f / 32.f) + 1e-6f);
#pragma unroll
    for (int c = 0; c < 32; c++) {
        a0[c] = fmaf((a0[c] - m0) * r0, s_lw[c], s_lb[c]);
        a1[c] = fmaf((a1[c] - m1) * r1, s_lw[c], s_lb[c]);
    }
    for (int oc = 0; oc < 96; oc++) {
        float acc0 = 0.f, acc1 = 0.f;
#pragma unroll
        for (int c = 0; c < 32; c++) {
            float w = s_w[oc * 32 + c];
            acc0 = fmaf(w, a0[c], acc0);
            acc1 = fmaf(w, a1[c], acc1);
        }
        float2 o; o.x = acc0; o.y = acc1;
        *(float2*)&g_qkv_pre[(size_t)(b * 96 + oc) * HWsz + p] = o;
    }
}

// ---------------- depthwise 3x3, pad=1, optional gelu ----------------
__global__ void dw3x3_k(const float* __restrict__ in, const float* __restrict__ w,
                        float* __restrict__ out, int Cn, int doGelu, size_t total)
{
    size_t idx = (size_t)blockIdx.x * blockDim.x + threadIdx.x;
    if (idx >= total) return;
    int x = (int)(idx % Ww);
    size_t t = idx / Ww;
    int y = (int)(t % Hh);
    int c = (int)((idx / HWsz) % Cn);
    const float* ip = in + (idx / HWsz) * HWsz;
    const float* wp = w + c * 9;
    float s = 0.f;
#pragma unroll
    for (int i = 0; i < 3; i++) {
        int yy = y + i - 1;
        if (yy < 0 || yy >= Hh) continue;
#pragma unroll
        for (int j = 0; j < 3; j++) {
            int xx = x + j - 1;
            if (xx < 0 || xx >= Ww) continue;
            s = fmaf(__ldg(&wp[i * 3 + j]), __ldg(&ip[(size_t)yy * Ww + xx]), s);
        }
    }
    if (doGelu) s = gelu_exact(s);
    out[idx] = s;
}

// ---------------- sum of squares per (q/k, b, ch32) ----------------
__global__ void sumsq_k() {
    int idx = blockIdx.x;              // 0..255
    int c = idx & 31;
    int b = (idx >> 5) & 3;
    int t = idx >> 7;                  // 0=q, 1=k
    const float* p = g_qkv + (size_t)(b * 96 + t * 32 + c) * HWsz;
    float s = 0.f;
    for (int i = threadIdx.x; i < HWsz; i += 256) { float v = p[i]; s = fmaf(v, v, s); }
    __shared__ float sh[256];
    sh[threadIdx.x] = s; __syncthreads();
    for (int o = 128; o; o >>= 1) {
        if (threadIdx.x < o) sh[threadIdx.x] += sh[threadIdx.x + o];
        __syncthreads();
    }
    if (threadIdx.x == 0) g_ssq[idx] = sh[0];
}

// ---------------- gram S[b][h][c][d] = sum_n q*k ----------------
__global__ void gram_k() {
    int idx = blockIdx.x;              // 0..511
    int d = idx & 3;
    int c = (idx >> 2) & 3;
    int h = (idx >> 4) & 7;
    int b = idx >> 7;
    const float* qp = g_qkv + (size_t)(b * 96 + h * 4 + c) * HWsz;
    const float* kp = g_qkv + (size_t)(b * 96 + 32 + h * 4 + d) * HWsz;
    float s = 0.f;
    for (int i = threadIdx.x; i < HWsz; i += 256) s = fmaf(qp[i], kp[i], s);
    __shared__ float sh[256];
    sh[threadIdx.x] = s; __syncthreads();
    for (int o = 128; o; o >>= 1) {
        if (threadIdx.x < o) sh[threadIdx.x] += sh[threadIdx.x + o];
        __syncthreads();
    }
    if (threadIdx.x == 0) g_S[idx] = sh[0];
}

// ---------------- normalize + temperature + softmax ----------------
__global__ void attn_k(const float* __restrict__ temp) {
    int t = threadIdx.x;
    if (t >= 32) return;
    int b = t >> 3, h = t & 7;
    float nq[4], nk[4];
#pragma unroll
    for (int c = 0; c < 4; c++) {
        nq[c] = fmaxf(sqrtf(g_ssq[0 * 128 + b * 32 + h * 4 + c]), 1e-12f);
        nk[c] = fmaxf(sqrtf(g_ssq[1 * 128 + b * 32 + h * 4 + c]), 1e-12f);
    }
    float tp = temp[h];
    float A[16];
#pragma unroll
    for (int c = 0; c < 4; c++)
#pragma unroll
        for (int d = 0; d < 4; d++)
            A[c * 4 + d] = g_S[(b * 8 + h) * 16 + c * 4 + d] / (nq[c] * nk[d]) * tp;
#pragma unroll
    for (int c = 0; c < 4; c++) {
        float m = A[c * 4];
#pragma unroll
        for (int d = 1; d < 4; d++) m = fmaxf(m, A[c * 4 + d]);
        float sum = 0.f;
#pragma unroll
        for (int d = 0; d < 4; d++) { A[c * 4 + d] = expf(A[c * 4 + d] - m); sum += A[c * 4 + d]; }
        float inv = 1.f / sum;
#pragma unroll
        for (int d = 0; d < 4; d++) g_attn[(b * 8 + h) * 16 + c * 4 + d] = A[c * 4 + d] * inv;
    }
}

// ---------------- fused: attn@v -> proj 1x1 -> +xb -> ff1 1x1 -> gelu ----------------
__global__ void __launch_bounds__(128) outproj_k(
    const float* __restrict__ projw, const float* __restrict__ ff1w)
{
    __shared__ float s_at[128], s_pw[1024], s_fw[1024];
    int b = blockIdx.z;
    int tid = threadIdx.x;
    for (int i = tid; i < 1024; i += 128) { s_pw[i] = projw[i]; s_fw[i] = ff1w[i]; }
    if (tid < 128) s_at[tid] = g_attn[b * 128 + tid];
    __syncthreads();

    int p = blockIdx.x * 128 + tid;   // exactly HWsz threads in grid.x*128
    float v[32];
#pragma unroll
    for (int c = 0; c < 32; c++)
        v[c] = g_qkv[(size_t)(b * 96 + 64 + c) * HWsz + p];
    float o[32];
#pragma unroll
    for (int c = 0; c < 32; c++) {
        int h = c >> 2, ci = c & 3;
        const float* at = &s_at[h * 16 + ci * 4];
        int vb = c & ~3;
        o[c] = at[0] * v[vb] + at[1] * v[vb + 1] + at[2] * v[vb + 2] + at[3] * v[vb + 3];
    }
    float y[32];
#pragma unroll
    for (int c = 0; c < 32; c++) {
        float acc = g_xb[(size_t)(b * 32 + c) * HWsz + p];
#pragma unroll
        for (int c2 = 0; c2 < 32; c2++)
            acc = fmaf(s_pw[c * 32 + c2], o[c2], acc);
        y[c] = acc;
    }
#pragma unroll
    for (int c = 0; c < 32; c++) {
        float acc = 0.f;
#pragma unroll
        for (int c2 = 0; c2 < 32; c2++)
            acc = fmaf(s_fw[c * 32 + c2], y[c2], acc);
        g_ff[(size_t)(b * 32 + c) * HWsz + p] = gelu_exact(acc);
    }
}

// ---------------- launch ----------------
extern "C" void kernel_launch(void* const* d_in, const int* in_sizes, int n_in,
                              void* d_out, int out_size)
{
    const float* x       = (const float*)d_in[0];
    const float* ln_w    = (const float*)d_in[1];
    const float* ln_b    = (const float*)d_in[2];
    const float* temper  = (const float*)d_in[3];
    const float* pw_w    = (const float*)d_in[4];
    const float* dw_w    = (const float*)d_in[5];
    const float* proj_w  = (const float*)d_in[6];
    const float* ff1_w   = (const float*)d_in[7];
    const float* ffdw_w  = (const float*)d_in[8];
    const float* det_w1  = (const float*)d_in[9];
    const float* det_b1  = (const float*)d_in[10];
    const float* det_w2  = (const float*)d_in[11];
    const float* det_b2  = (const float*)d_in[12];
    const float* det_w3  = (const float*)d_in[13];
    const float* det_b3  = (const float*)d_in[14];
    const float* det_fcw = (const float*)d_in[15];
    const float* det_fcb = (const float*)d_in[16];
    const float* hvi_w1  = (const float*)d_in[17];
    const float* hvi_b1  = (const float*)d_in[18];
    const float* hvi_w2  = (const float*)d_in[19];
    const float* hvi_b2  = (const float*)d_in[20];
    const float* ycc_w1  = (const float*)d_in[21];
    const float* ycc_b1  = (const float*)d_in[22];
    const float* ycc_w2  = (const float*)d_in[23];
    const float* ycc_b2  = (const float*)d_in[24];
    float* outp = (float*)d_out;

    float *p_det1, *p_det2, *p_pool, *p_xb, *p_qkv_pre, *p_qkv;
    int* p_sel;
    cudaGetSymbolAddress((void**)&p_det1, g_det1);
    cudaGetSymbolAddress((void**)&p_det2, g_det2);
    cudaGetSymbolAddress((void**)&p_pool, g_pool);
    cudaGetSymbolAddress((void**)&p_sel,  g_sel);
    cudaGetSymbolAddress((void**)&p_xb,   g_xb);
    cudaGetSymbolAddress((void**)&p_qkv_pre, g_qkv_pre);
    cudaGetSymbolAddress((void**)&p_qkv,  g_qkv);
    float* p_ff;
    cudaGetSymbolAddress((void**)&p_ff, g_ff);

    dim3 blk(32, 4);

    // detector (batch 0 only!)
    zero_pool_k<<<1, 256>>>();
    conv3x3_k<32, false><<<dim3(12, 96, 4),  blk>>>(x,      det_w1, det_b1, p_det1, 64,  1, nullptr, 0);
    conv3x3_k<64, false><<<dim3(12, 96, 8),  blk>>>(p_det1, det_w2, det_b2, p_det2, 128, 1, nullptr, 0);
    conv3x3_k<128, true><<<dim3(12, 96, 16), blk>>>(p_det2, det_w3, det_b3, p_pool, 256, 1, nullptr, 0);
    logits_k<<<1, 32>>>(det_fcw, det_fcb);

    // branch (predicated on g_sel; only the selected path does work)
    copy_rgb_k<<<(NB * 32 * HWsz / 4 + 1023) / 1024, 1024>>>(x);
    conv3x3_k<32, false><<<dim3(12, 96, 16), blk>>>(x,      hvi_w1, hvi_b1, p_det1, 64, 1, p_sel, 1);
    conv3x3_k<64, false><<<dim3(12, 96, 8),  blk>>>(p_det1, hvi_w2, hvi_b2, p_xb,   32, 1, p_sel, 1);
    conv3x3_k<32, false><<<dim3(12, 96, 16), blk>>>(x,      ycc_w1, ycc_b1, p_det1, 64, 1, p_sel, 2);
    conv3x3_k<64, false><<<dim3(12, 96, 8),  blk>>>(p_det1, ycc_w2, ycc_b2, p_xb,   32, 1, p_sel, 2);

    // LN + pw 1x1 -> qkv_pre
    ln_pw_k<<<(NB * HWsz / 2) / 128, 128>>>(ln_w, ln_b, pw_w);
    // depthwise 3x3 -> qkv
    {
        size_t total = (size_t)NB * 96 * HWsz;
        dw3x3_k<<<(unsigned)((total + 255) / 256), 256>>>(p_qkv_pre, dw_w, p_qkv, 96, 0, total);
    }
    // norms, gram, softmax
    sumsq_k<<<256, 256>>>();
    gram_k<<<512, 256>>>();
    attn_k<<<1, 32>>>(temper);
    // attn apply + proj + residual + ff1 + gelu
    outproj_k<<<dim3(HWsz / 128, 1, NB), 128>>>(proj_w, ff1_w);
    // ffdw depthwise + gelu -> out
    {
        size_t total = (size_t)NB * 32 * HWsz;
        dw3x3_k<<<(unsigned)((total + 255) / 256), 256>>>(p_ff, ffdw_w, outp, 32, 1, total);
    }
    (void)in_sizes; (void)n_in; (void)out_size;
}

// round 2
// speedup vs baseline: 2.0465x; 2.0465x over previous
#include <cuda_runtime.h>
#include <cuda_bf16.h>
#include <cstdint>
#include <math.h>

#define Hh 384
#define Ww 384
#define HWsz 147456
#define NB 4

// ---------------- static device scratch (no allocations allowed) ----------------
static __device__ float g_det1[(size_t)NB * 64 * HWsz];   // branch temp (fp32 NCHW)
static __device__ float g_pool[256];                      // det conv3 global-sum (batch 0)
static __device__ int   g_sel[1];                         // branch selection
static __device__ float g_xb[(size_t)NB * 32 * HWsz];     // branch output
static __device__ float g_qkv_pre[(size_t)NB * 96 * HWsz];
static __device__ float g_qkv[(size_t)NB * 96 * HWsz];
static __device__ float g_ssq[256];                       // [qk][b][32] sum of squares
static __device__ float g_S[512];                         // [b][h][4][4] gram
static __device__ float g_attn[512];                      // softmaxed attention
static __device__ float g_ff[(size_t)NB * 32 * HWsz];     // after ff1+gelu

// bf16 detector path (batch 0 only)
static __device__ __nv_bfloat16 g_det1h[(size_t)HWsz * 64];    // NHWC
static __device__ __nv_bfloat16 g_det2h[(size_t)HWsz * 128];   // NHWC
static __device__ __nv_bfloat16 g_wbf2[2 * 2 * 9 * 64 * 40];   // det2 weights bf16, smem-mirror layout
static __device__ __nv_bfloat16 g_wbf3[4 * 4 * 9 * 64 * 40];   // det3 weights bf16

__device__ __forceinline__ float gelu_exact(float x) {
    return 0.5f * x * (1.0f + erff(x * 0.70710678118654752f));
}

// ---------------- generic 3x3 conv, pad=1 (fp32 direct) ----------------
// block: 32x4 threads; tile: 32W x 4H x 16 oc; each thread: 4 rows x 4 ocs.
// POOL variant fuses bias+relu+global sum. OUTBF16NHWC writes bf16 NHWC.
template<int CIN, bool POOL, bool OUTBF16NHWC = false>
__global__ void __launch_bounds__(128) conv3x3_k(
    const float* __restrict__ in, const float* __restrict__ w,
    const float* __restrict__ bias, float* __restrict__ out,
    int Cout, int doRelu, const int* selp, int selv)
{
    if (selp && __ldg(selp) != selv) return;
    const int tx = threadIdx.x;
    const int ty = threadIdx.y;
    const int x0 = blockIdx.x * 32;
    const int y0 = blockIdx.y * 4;
    const int ocGroups = Cout >> 4;
    const int b   = blockIdx.z / ocGroups;
    const int ocb = (blockIdx.z % ocGroups) << 4;

    __shared__ float s_in[4][6][34];
    __shared__ float s_w[16][4][9];

    const float* inb = in + (size_t)b * CIN * HWsz;
    float acc[4][4];
#pragma unroll
    for (int r = 0; r < 4; r++)
#pragma unroll
        for (int o = 0; o < 4; o++) acc[r][o] = 0.f;

    const int tid = ty * 32 + tx;
    for (int cin0 = 0; cin0 < CIN; cin0 += 4) {
        for (int idx = tid; idx < 4 * 6 * 34; idx += 128) {
            int cc  = idx / 204;
            int rem = idx - cc * 204;
            int r   = rem / 34;
            int col = rem - r * 34;
            int gr = y0 + r - 1;
            int gc = x0 + col - 1;
            float v = 0.f;
            if (gr >= 0 && gr < Hh && gc >= 0 && gc < Ww)
                v = inb[(size_t)(cin0 + cc) * HWsz + gr * Ww + gc];
            s_in[cc][r][col] = v;
        }
        for (int idx = tid; idx < 16 * 4 * 9; idx += 128) {
            int oc  = idx / 36;
            int rem = idx - oc * 36;
            int cc  = rem / 9;
            int k   = rem - cc * 9;
            s_w[oc][cc][k] = w[((size_t)(ocb + oc) * CIN + cin0 + cc) * 9 + k];
        }
        __syncthreads();
#pragma unroll
        for (int cc = 0; cc < 4; cc++) {
            float xin[6][3];
#pragma unroll
            for (int r = 0; r < 6; r++)
#pragma unroll
                for (int j = 0; j < 3; j++)
                    xin[r][j] = s_in[cc][r][tx + j];
#pragma unroll
            for (int o = 0; o < 4; o++) {
                float wv[9];
#pragma unroll
                for (int k = 0; k < 9; k++) wv[k] = s_w[ty * 4 + o][cc][k];
#pragma unroll
                for (int r = 0; r < 4; r++) {
                    float s = acc[r][o];
                    s = fmaf(wv[0], xin[r    ][0], s);
                    s = fmaf(wv[1], xin[r    ][1], s);
                    s = fmaf(wv[2], xin[r    ][2], s);
                    s = fmaf(wv[3], xin[r + 1][0], s);
                    s = fmaf(wv[4], xin[r + 1][1], s);
                    s = fmaf(wv[5], xin[r + 1][2], s);
                    s = fmaf(wv[6], xin[r + 2][0], s);
                    s = fmaf(wv[7], xin[r + 2][1], s);
                    s = fmaf(wv[8], xin[r + 2][2], s);
                    acc[r][o] = s;
                }
            }
        }
        __syncthreads();
    }

    if (!POOL) {
#pragma unroll
        for (int o = 0; o < 4; o++) {
            int oc = ocb + ty * 4 + o;
            float bv = bias ? bias[oc] : 0.f;
#pragma unroll
            for (int r = 0; r < 4; r++) {
                float v = acc[r][o] + bv;
                if (doRelu) v = fmaxf(v, 0.f);
                if (OUTBF16NHWC) {
                    __nv_bfloat16* ob = (__nv_bfloat16*)out;
                    ob[((size_t)(y0 + r) * Ww + x0 + tx) * Cout + oc] = __float2bfloat16(v);
                } else {
                    out[(size_t)(b * Cout + oc) * HWsz + (size_t)(y0 + r) * Ww + x0 + tx] = v;
                }
            }
        }
    } else {
#pragma unroll
        for (int o = 0; o < 4; o++) {
            int oc = ocb + ty * 4 + o;
            float bv = bias[oc];
            float s = 0.f;
#pragma unroll
            for (int r = 0; r < 4; r++) s += fmaxf(acc[r][o] + bv, 0.f);
#pragma unroll
            for (int off = 16; off; off >>= 1)
                s += __shfl_down_sync(0xffffffffu, s, off);
            if (tx == 0) atomicAdd(&out[oc], s);
        }
    }
}

// ---------------- weight pre-conversion fp32 -> bf16 smem-mirror layout ----------------
// dst[((ot*(CIN/32)+kc)*9 + tap)*64*40 + oc*40 + c]
__global__ void cvtw_k(const float* __restrict__ w, __nv_bfloat16* __restrict__ dst,
                       int Cout, int CIN)
{
    int idx = blockIdx.x * 256 + threadIdx.x;
    int total = Cout * CIN * 9;
    if (idx >= total) return;
    int ocg = idx / (CIN * 9);
    int rem = idx - ocg * (CIN * 9);
    int cin = rem / 9, tap = rem % 9;
    int ot = ocg >> 6, oc = ocg & 63;
    int kc = cin >> 5, c = cin & 31;
    dst[((((size_t)ot * (CIN / 32) + kc) * 9 + tap) * 64 + oc) * 40 + c] = __float2bfloat16(w[idx]);
}

// ---------------- bf16 HMMA implicit-GEMM 3x3 conv (pad=1) ----------------
// Tile: 64 oc x 64 px (one output row). 8 warps: warp = (m16 slice 0..3, n32 half 0..1).
// SMEM: input pixel-major [3 rows][66 px][40 halves (32 used)], weights [3 taps][64 oc][40].
// Taps processed as 3 groups of 3 (one dy row each) to fit 48KB static smem.
template<int CIN, bool POOL>
__global__ void __launch_bounds__(256) mmaconv_k(
    const __nv_bfloat16* __restrict__ in,    // NHWC [384*384][CIN]
    const __nv_bfloat16* __restrict__ wbf,   // [ot][kc][tap][64][40]
    const float* __restrict__ bias,
    __nv_bfloat16* __restrict__ outNHWC,     // !POOL
    float* __restrict__ pool,                // POOL
    int Cout)
{
    const int tid  = threadIdx.x;
    const int lane = tid & 31, warp = tid >> 5;
    const int x0 = blockIdx.x * 64;
    const int y  = blockIdx.y;
    const int ot = blockIdx.z;
    const int oc0 = ot * 64;
    const int m0 = (warp & 3) << 4;     // 0,16,32,48
    const int nb = (warp >> 2) << 5;    // 0 or 32

    __shared__ __align__(16) unsigned char smraw[15840 + 15360];
    char* sInB = (char*)smraw;               // bf16 [(dy*66+px)*40 + c]
    char* sWB  = (char*)smraw + 15840;       // bf16 [(tt*64+oc)*40 + c]

    float acc[4][4];
#pragma unroll
    for (int nt = 0; nt < 4; nt++)
#pragma unroll
        for (int c = 0; c < 4; c++) acc[nt][c] = 0.f;

    const int KC = CIN / 32;
    for (int kc = 0; kc < KC; kc++) {
        __syncthreads();
        // stage input: 3 rows x 66 px x 32 cin bf16, 16B chunks
        for (int idx = tid; idx < 792; idx += 256) {
            int dy = idx / 264; int r = idx - dy * 264;
            int px = r >> 2, cg = r & 3;
            int gy = y + dy - 1, gx = x0 - 1 + px;
            uint4 v = make_uint4(0u, 0u, 0u, 0u);
            if ((unsigned)gy < 384u && (unsigned)gx < 384u)
                v = *(const uint4*)(in + ((size_t)(gy * 384 + gx)) * CIN + kc * 32 + cg * 8);
            *(uint4*)(sInB + ((dy * 66 + px) * 40 + cg * 8) * 2) = v;
        }
        const uint4* wsrc = (const uint4*)(wbf + ((size_t)(ot * KC + kc) * 9) * 64 * 40);
#pragma unroll
        for (int tg = 0; tg < 3; tg++) {       // tap row group: dy = tg
            if (tg) __syncthreads();
            for (int idx = tid; idx < 960; idx += 256)
                ((uint4*)sWB)[idx] = wsrc[tg * 960 + idx];
            __syncthreads();
#pragma unroll
            for (int tt = 0; tt < 3; tt++) {   // dx = tt
#pragma unroll
                for (int k16 = 0; k16 < 2; k16++) {
                    int aoff = (tt * 64 + m0 + (lane >> 2)) * 40 + k16 * 16 + (lane & 3) * 2;
                    uint32_t a0 = *(const uint32_t*)(sWB + aoff * 2);
                    uint32_t a1 = *(const uint32_t*)(sWB + (aoff + 8 * 40) * 2);
                    uint32_t a2 = *(const uint32_t*)(sWB + (aoff + 8) * 2);
                    uint32_t a3 = *(const uint32_t*)(sWB + (aoff + 8 * 40 + 8) * 2);
#pragma unroll
                    for (int nt = 0; nt < 4; nt++) {
                        int px = nb + nt * 8 + (lane >> 2) + tt;
                        int boff = (tg * 66 + px) * 40 + k16 * 16 + (lane & 3) * 2;
                        uint32_t b0 = *(const uint32_t*)(sInB + boff * 2);
                        uint32_t b1 = *(const uint32_t*)(sInB + (boff + 8) * 2);
                        asm volatile(
                            "mma.sync.aligned.m16n8k16.row.col.f32.bf16.bf16.f32 "
                            "{%0,%1,%2,%3},{%4,%5,%6,%7},{%8,%9},{%0,%1,%2,%3};\n"
                            : "+f"(acc[nt][0]), "+f"(acc[nt][1]),
                              "+f"(acc[nt][2]), "+f"(acc[nt][3])
                            : "r"(a0), "r"(a1), "r"(a2), "r"(a3), "r"(b0), "r"(b1));
                    }
                }
            }
        }
    }
    __syncthreads();

    float blo = __ldg(&bias[oc0 + m0 + (lane >> 2)]);
    float bhi = __ldg(&bias[oc0 + m0 + (lane >> 2) + 8]);

    if (POOL) {
        float slo = 0.f, shi = 0.f;
#pragma unroll
        for (int nt = 0; nt < 4; nt++) {
            slo += fmaxf(acc[nt][0] + blo, 0.f) + fmaxf(acc[nt][1] + blo, 0.f);
            shi += fmaxf(acc[nt][2] + bhi, 0.f) + fmaxf(acc[nt][3] + bhi, 0.f);
        }
        slo += __shfl_xor_sync(0xffffffffu, slo, 1);
        slo += __shfl_xor_sync(0xffffffffu, slo, 2);
        shi += __shfl_xor_sync(0xffffffffu, shi, 1);
        shi += __shfl_xor_sync(0xffffffffu, shi, 2);
        if ((lane & 3) == 0) {
            atomicAdd(&pool[oc0 + m0 + (lane >> 2)], slo);
            atomicAdd(&pool[oc0 + m0 + (lane >> 2) + 8], shi);
        }
    } else {
        __nv_bfloat16* sOut = (__nv_bfloat16*)smraw;   // [px 64][oc 64]
#pragma unroll
        for (int nt = 0; nt < 4; nt++) {
            int px = nb + nt * 8 + (lane & 3) * 2;
            int oc = m0 + (lane >> 2);
            sOut[px * 64 + oc]           = __float2bfloat16(fmaxf(acc[nt][0] + blo, 0.f));
            sOut[(px + 1) * 64 + oc]     = __float2bfloat16(fmaxf(acc[nt][1] + blo, 0.f));
            sOut[px * 64 + oc + 8]       = __float2bfloat16(fmaxf(acc[nt][2] + bhi, 0.f));
            sOut[(px + 1) * 64 + oc + 8] = __float2bfloat16(fmaxf(acc[nt][3] + bhi, 0.f));
        }
        __syncthreads();
        for (int idx = tid; idx < 512; idx += 256) {
            int px = idx >> 3, og = idx & 7;
            *(uint4*)(outNHWC + ((size_t)(y * 384 + x0 + px)) * Cout + oc0 + og * 8) =
                *(const uint4*)(sOut + px * 64 + og * 8);
        }
    }
}

// ---------------- zero pool ----------------
__global__ void zero_pool_k() {
    if (threadIdx.x < 256) g_pool[threadIdx.x] = 0.f;
}

// ---------------- logits + argmax (batch 0 only) ----------------
__global__ void logits_k(const float* __restrict__ fcw, const float* __restrict__ fcb) {
    __shared__ float l[3];
    int t = threadIdx.x;
    if (t < 3) {
        float s = 0.f;
        const float inv = 1.0f / (float)HWsz;
        for (int k = 0; k < 256; k++)
            s = fmaf(fcw[t * 256 + k], g_pool[k] * inv, s);
        l[t] = s + fcb[t];
    }
    __syncthreads();
    if (t == 0) {
        int best = 0; float bv = l[0];
        if (l[1] > bv) { bv = l[1]; best = 1; }
        if (l[2] > bv) { bv = l[2]; best = 2; }
        g_sel[0] = best;
    }
}

// ---------------- rgb branch: xb = x (predicated sel==0) ----------------
__global__ void copy_rgb_k(const float* __restrict__ x) {
    if (__ldg(g_sel) != 0) return;
    size_t i = (size_t)blockIdx.x * blockDim.x + threadIdx.x;
    const float4* src = (const float4*)x;
    float4* dst = (float4*)g_xb;
    size_t n4 = (size_t)NB * 32 * HWsz / 4;
    if (i < n4) dst[i] = src[i];
}

// ---------------- fused channels-first LayerNorm + 1x1 pwconv (C=32 -> 96), 2 px/thread ----------------
__global__ void __launch_bounds__(128) ln_pw_k(
    const float* __restrict__ lnw, const float* __restrict__ lnb,
    const float* __restrict__ pww)
{
    __shared__ float s_w[96 * 32];
    __shared__ float s_lw[32], s_lb[32];
    int tid = threadIdx.x;
    for (int i = tid; i < 96 * 32; i += 128) s_w[i] = pww[i];
    if (tid < 32) { s_lw[tid] = lnw[tid]; s_lb[tid] = lnb[tid]; }
    __syncthreads();

    size_t pair = (size_t)blockIdx.x * 128 + tid;
    size_t gp = pair * 2;
    int b = (int)(gp / HWsz);
    int p = (int)(gp % HWsz);

    float a0[32], a1[32];
    float m0 = 0.f, m1 = 0.f;
#pragma unroll
    for (int c = 0; c < 32; c++) {
        float2 v = *(const float2*)&g_xb[(size_t)(b * 32 + c) * HWsz + p];
        a0[c] = v.x; a1[c] = v.y;
        m0 += v.x; m1 += v.y;
    }
    m0 *= (1.f / 32.f); m1 *= (1.f / 32.f);
    float v0 = 0.f, v1 = 0.f;
#pragma unroll
    for (int c = 0; c < 32; c++) {
        float d0 = a0[c] - m0, d1 = a1[c] - m1;
        v0 = fmaf(d0, d0, v0); v1 = fmaf(d1, d1, v1);
    }
    float r0 = rsqrtf(v0 * (1.f / 32.f) + 1e-6f);
    float r1 = rsqrtf(v1 * (1.f / 32.f) + 1e-6f);
#pragma unroll
    for (int c = 0; c < 32; c++) {
        a0[c] = fmaf((a0[c] - m0) * r0, s_lw[c], s_lb[c]);
        a1[c] = fmaf((a1[c] - m1) * r1, s_lw[c], s_lb[c]);
    }
    for (int oc = 0; oc < 96; oc++) {
        float acc0 = 0.f, acc1 = 0.f;
#pragma unroll
        for (int c = 0; c < 32; c++) {
            float w = s_w[oc * 32 + c];
            acc0 = fmaf(w, a0[c], acc0);
            acc1 = fmaf(w, a1[c], acc1);
        }
        float2 o; o.x = acc0; o.y = acc1;
        *(float2*)&g_qkv_pre[(size_t)(b * 96 + oc) * HWsz + p] = o;
    }
}

// ---------------- depthwise 3x3, pad=1, optional gelu ----------------
__global__ void dw3x3_k(const float* __restrict__ in, const float* __restrict__ w,
                        float* __restrict__ out, int Cn, int doGelu, size_t total)
{
    size_t idx = (size_t)blockIdx.x * blockDim.x + threadIdx.x;
    if (idx >= total) return;
    int x = (int)(idx % Ww);
    size_t t = idx / Ww;
    int y = (int)(t % Hh);
    int c = (int)((idx / HWsz) % Cn);
    const float* ip = in + (idx / HWsz) * HWsz;
    const float* wp = w + c * 9;
    float s = 0.f;
#pragma unroll
    for (int i = 0; i < 3; i++) {
        int yy = y + i - 1;
        if (yy < 0 || yy >= Hh) continue;
#pragma unroll
        for (int j = 0; j < 3; j++) {
            int xx = x + j - 1;
            if (xx < 0 || xx >= Ww) continue;
            s = fmaf(__ldg(&wp[i * 3 + j]), __ldg(&ip[(size_t)yy * Ww + xx]), s);
        }
    }
    if (doGelu) s = gelu_exact(s);
    out[idx] = s;
}

// ---------------- sum of squares per (q/k, b, ch32) ----------------
__global__ void sumsq_k() {
    int idx = blockIdx.x;
    int c = idx & 31;
    int b = (idx >> 5) & 3;
    int t = idx >> 7;
    const float* p = g_qkv + (size_t)(b * 96 + t * 32 + c) * HWsz;
    float s = 0.f;
    for (int i = threadIdx.x; i < HWsz; i += 256) { float v = p[i]; s = fmaf(v, v, s); }
    __shared__ float sh[256];
    sh[threadIdx.x] = s; __syncthreads();
    for (int o = 128; o; o >>= 1) {
        if (threadIdx.x < o) sh[threadIdx.x] += sh[threadIdx.x + o];
        __syncthreads();
    }
    if (threadIdx.x == 0) g_ssq[idx] = sh[0];
}

// ---------------- gram S[b][h][c][d] = sum_n q*k ----------------
__global__ void gram_k() {
    int idx = blockIdx.x;
    int d = idx & 3;
    int c = (idx >> 2) & 3;
    int h = (idx >> 4) & 7;
    int b = idx >> 7;
    const float* qp = g_qkv + (size_t)(b * 96 + h * 4 + c) * HWsz;
    const float* kp = g_qkv + (size_t)(b * 96 + 32 + h * 4 + d) * HWsz;
    float s = 0.f;
    for (int i = threadIdx.x; i < HWsz; i += 256) s = fmaf(qp[i], kp[i], s);
    __shared__ float sh[256];
    sh[threadIdx.x] = s; __syncthreads();
    for (int o = 128; o; o >>= 1) {
        if (threadIdx.x < o) sh[threadIdx.x] += sh[threadIdx.x + o];
        __syncthreads();
    }
    if (threadIdx.x == 0) g_S[idx] = sh[0];
}

// ---------------- normalize + temperature + softmax ----------------
__global__ void attn_k(const float* __restrict__ temp) {
    int t = threadIdx.x;
    if (t >= 32) return;
    int b = t >> 3, h = t & 7;
    float nq[4], nk[4];
#pragma unroll
    for (int c = 0; c < 4; c++) {
        nq[c] = fmaxf(sqrtf(g_ssq[0 * 128 + b * 32 + h * 4 + c]), 1e-12f);
        nk[c] = fmaxf(sqrtf(g_ssq[1 * 128 + b * 32 + h * 4 + c]), 1e-12f);
    }
    float tp = temp[h];
    float A[16];
#pragma unroll
    for (int c = 0; c < 4; c++)
#pragma unroll
        for (int d = 0; d < 4; d++)
            A[c * 4 + d] = g_S[(b * 8 + h) * 16 + c * 4 + d] / (nq[c] * nk[d]) * tp;
#pragma unroll
    for (int c = 0; c < 4; c++) {
        float m = A[c * 4];
#pragma unroll
        for (int d = 1; d < 4; d++) m = fmaxf(m, A[c * 4 + d]);
        float sum = 0.f;
#pragma unroll
        for (int d = 0; d < 4; d++) { A[c * 4 + d] = expf(A[c * 4 + d] - m); sum += A[c * 4 + d]; }
        float inv = 1.f / sum;
#pragma unroll
        for (int d = 0; d < 4; d++) g_attn[(b * 8 + h) * 16 + c * 4 + d] = A[c * 4 + d] * inv;
    }
}

// ---------------- fused: attn@v -> proj 1x1 -> +xb -> ff1 1x1 -> gelu ----------------
__global__ void __launch_bounds__(128) outproj_k(
    const float* __restrict__ projw, const float* __restrict__ ff1w)
{
    __shared__ float s_at[128], s_pw[1024], s_fw[1024];
    int b = blockIdx.z;
    int tid = threadIdx.x;
    for (int i = tid; i < 1024; i += 128) { s_pw[i] = projw[i]; s_fw[i] = ff1w[i]; }
    if (tid < 128) s_at[tid] = g_attn[b * 128 + tid];
    __syncthreads();

    int p = blockIdx.x * 128 + tid;
    float v[32];
#pragma unroll
    for (int c = 0; c < 32; c++)
        v[c] = g_qkv[(size_t)(b * 96 + 64 + c) * HWsz + p];
    float o[32];
#pragma unroll
    for (int c = 0; c < 32; c++) {
        int h = c >> 2, ci = c & 3;
        const float* at = &s_at[h * 16 + ci * 4];
        int vb = c & ~3;
        o[c] = at[0] * v[vb] + at[1] * v[vb + 1] + at[2] * v[vb + 2] + at[3] * v[vb + 3];
    }
    float y[32];
#pragma unroll
    for (int c = 0; c < 32; c++) {
        float acc = g_xb[(size_t)(b * 32 + c) * HWsz + p];
#pragma unroll
        for (int c2 = 0; c2 < 32; c2++)
            acc = fmaf(s_pw[c * 32 + c2], o[c2], acc);
        y[c] = acc;
    }
#pragma unroll
    for (int c = 0; c < 32; c++) {
        float acc = 0.f;
#pragma unroll
        for (int c2 = 0; c2 < 32; c2++)
            acc = fmaf(s_fw[c * 32 + c2], y[c2], acc);
        g_ff[(size_t)(b * 32 + c) * HWsz + p] = gelu_exact(acc);
    }
}

// ---------------- launch ----------------
extern "C" void kernel_launch(void* const* d_in, const int* in_sizes, int n_in,
                              void* d_out, int out_size)
{
    const float* x       = (const float*)d_in[0];
    const float* ln_w    = (const float*)d_in[1];
    const float* ln_b    = (const float*)d_in[2];
    const float* temper  = (const float*)d_in[3];
    const float* pw_w    = (const float*)d_in[4];
    const float* dw_w    = (const float*)d_in[5];
    const float* proj_w  = (const float*)d_in[6];
    const float* ff1_w   = (const float*)d_in[7];
    const float* ffdw_w  = (const float*)d_in[8];
    const float* det_w1  = (const float*)d_in[9];
    const float* det_b1  = (const float*)d_in[10];
    const float* det_w2  = (const float*)d_in[11];
    const float* det_b2  = (const float*)d_in[12];
    const float* det_w3  = (const float*)d_in[13];
    const float* det_b3  = (const float*)d_in[14];
    const float* det_fcw = (const float*)d_in[15];
    const float* det_fcb = (const float*)d_in[16];
    const float* hvi_w1  = (const float*)d_in[17];
    const float* hvi_b1  = (const float*)d_in[18];
    const float* hvi_w2  = (const float*)d_in[19];
    const float* hvi_b2  = (const float*)d_in[20];
    const float* ycc_w1  = (const float*)d_in[21];
    const float* ycc_b1  = (const float*)d_in[22];
    const float* ycc_w2  = (const float*)d_in[23];
    const float* ycc_b2  = (const float*)d_in[24];
    float* outp = (float*)d_out;

    float *p_det1, *p_pool, *p_xb, *p_qkv_pre, *p_qkv, *p_ff;
    int* p_sel;
    __nv_bfloat16 *p_det1h, *p_det2h, *p_wbf2, *p_wbf3;
    cudaGetSymbolAddress((void**)&p_det1, g_det1);
    cudaGetSymbolAddress((void**)&p_pool, g_pool);
    cudaGetSymbolAddress((void**)&p_sel,  g_sel);
    cudaGetSymbolAddress((void**)&p_xb,   g_xb);
    cudaGetSymbolAddress((void**)&p_qkv_pre, g_qkv_pre);
    cudaGetSymbolAddress((void**)&p_qkv,  g_qkv);
    cudaGetSymbolAddress((void**)&p_ff,   g_ff);
    cudaGetSymbolAddress((void**)&p_det1h, g_det1h);
    cudaGetSymbolAddress((void**)&p_det2h, g_det2h);
    cudaGetSymbolAddress((void**)&p_wbf2, g_wbf2);
    cudaGetSymbolAddress((void**)&p_wbf3, g_wbf3);

    dim3 blk(32, 4);

    // weight pre-conversion for tensor-core detector convs
    cvtw_k<<<(128 * 64 * 9 + 255) / 256, 256>>>(det_w2, p_wbf2, 128, 64);
    cvtw_k<<<(256 * 128 * 9 + 255) / 256, 256>>>(det_w3, p_wbf3, 256, 128);
    zero_pool_k<<<1, 256>>>();

    // detector (batch 0 only): det1 fp32 direct -> bf16 NHWC; det2/det3 bf16 HMMA
    conv3x3_k<32, false, true><<<dim3(12, 96, 4), blk>>>(x, det_w1, det_b1, (float*)p_det1h, 64, 1, nullptr, 0);
    mmaconv_k<64,  false><<<dim3(6, 384, 2), 256>>>(p_det1h, p_wbf2, det_b2, p_det2h, nullptr, 128);
    mmaconv_k<128, true ><<<dim3(6, 384, 4), 256>>>(p_det2h, p_wbf3, det_b3, nullptr, p_pool, 256);
    logits_k<<<1, 32>>>(det_fcw, det_fcb);

    // branch (predicated on g_sel; only the selected path does work)
    copy_rgb_k<<<(NB * 32 * HWsz / 4 + 1023) / 1024, 1024>>>(x);
    conv3x3_k<32, false><<<dim3(12, 96, 16), blk>>>(x,      hvi_w1, hvi_b1, p_det1, 64, 1, p_sel, 1);
    conv3x3_k<64, false><<<dim3(12, 96, 8),  blk>>>(p_det1, hvi_w2, hvi_b2, p_xb,   32, 1, p_sel, 1);
    conv3x3_k<32, false><<<dim3(12, 96, 16), blk>>>(x,      ycc_w1, ycc_b1, p_det1, 64, 1, p_sel, 2);
    conv3x3_k<64, false><<<dim3(12, 96, 8),  blk>>>(p_det1, ycc_w2, ycc_b2, p_xb,   32, 1, p_sel, 2);

    // LN + pw 1x1 -> qkv_pre
    ln_pw_k<<<(NB * HWsz / 2) / 128, 128>>>(ln_w, ln_b, pw_w);
    // depthwise 3x3 -> qkv
    {
        size_t total = (size_t)NB * 96 * HWsz;
        dw3x3_k<<<(unsigned)((total + 255) / 256), 256>>>(p_qkv_pre, dw_w, p_qkv, 96, 0, total);
    }
    // norms, gram, softmax
    sumsq_k<<<256, 256>>>();
    gram_k<<<512, 256>>>();
    attn_k<<<1, 32>>>(temper);
    // attn apply + proj + residual + ff1 + gelu
    outproj_k<<<dim3(HWsz / 128, 1, NB), 128>>>(proj_w, ff1_w);
    // ffdw depthwise + gelu -> out
    {
        size_t total = (size_t)NB * 32 * HWsz;
        dw3x3_k<<<(unsigned)((total + 255) / 256), 256>>>(p_ff, ffdw_w, outp, 32, 1, total);
    }
    (void)in_sizes; (void)n_in; (void)out_size;
}

// round 3
// speedup vs baseline: 2.7323x; 1.3351x over previous
#include <cuda_runtime.h>
#include <cuda_bf16.h>
#include <cstdint>
#include <math.h>

#define Hh 384
#define Ww 384
#define HWsz 147456
#define NB 4

// ---------------- static device scratch ----------------
static __device__ float g_det1[(size_t)NB * 64 * HWsz];   // branch temp (fp32 NCHW)
static __device__ float g_pool[256];
static __device__ int   g_sel[1];
static __device__ float g_xb[(size_t)NB * 32 * HWsz];
static __device__ float g_qkv_pre[(size_t)NB * 96 * HWsz];
static __device__ float g_qkv[(size_t)NB * 96 * HWsz];
static __device__ float g_ssq[256];
static __device__ float g_S[512];
static __device__ float g_attn[512];
static __device__ float g_ff[(size_t)NB * 32 * HWsz];

// bf16 detector path (batch 0 only)
static __device__ __nv_bfloat16 g_xh[(size_t)HWsz * 32];        // x batch0 NHWC bf16
static __device__ __nv_bfloat16 g_det1h[(size_t)HWsz * 64];
static __device__ __nv_bfloat16 g_det2h[(size_t)HWsz * 128];
static __device__ __nv_bfloat16 g_wbf1[9 * 64 * 40];
static __device__ __nv_bfloat16 g_wbf2[2 * 2 * 9 * 64 * 40];
static __device__ __nv_bfloat16 g_wbf3[4 * 4 * 9 * 64 * 40];

__device__ __forceinline__ float gelu_exact(float x) {
    return 0.5f * x * (1.0f + erff(x * 0.70710678118654752f));
}

// ---- packed f32x2 helpers ----
__device__ __forceinline__ unsigned long long pk2(float v) {
    unsigned long long r;
    asm("mov.b64 %0, {%1, %1};" : "=l"(r) : "f"(v));
    return r;
}
__device__ __forceinline__ void ffma2(unsigned long long& a, unsigned long long x, unsigned long long w) {
    asm("fma.rn.f32x2 %0, %1, %2, %0;" : "+l"(a) : "l"(x), "l"(w));
}
__device__ __forceinline__ float2 upk2(unsigned long long a) {
    float2 f;
    asm("mov.b64 {%0, %1}, %2;" : "=f"(f.x), "=f"(f.y) : "l"(a));
    return f;
}

// ---------------- fp32 3x3 conv with packed f32x2 FMA (branch path) ----------------
// block 32x4; tile 32W x 4H x 16 oc; thread: 4 rows x 2 oc-pairs.
template<int CIN>
__global__ void __launch_bounds__(128) conv3x3_p2_k(
    const float* __restrict__ in, const float* __restrict__ w,
    const float* __restrict__ bias, float* __restrict__ out,
    int Cout, const int* selp, int selv)
{
    if (selp && __ldg(selp) != selv) return;
    const int tx = threadIdx.x;
    const int ty = threadIdx.y;
    const int x0 = blockIdx.x * 32;
    const int y0 = blockIdx.y * 4;
    const int ocGroups = Cout >> 4;
    const int b   = blockIdx.z / ocGroups;
    const int ocb = (blockIdx.z % ocGroups) << 4;

    __shared__ float  s_in[4][6][34];
    __shared__ float2 s_w2[8][4][9];

    const float* inb = in + (size_t)b * CIN * HWsz;
    unsigned long long acc2[4][2];
#pragma unroll
    for (int r = 0; r < 4; r++) { acc2[r][0] = 0ULL; acc2[r][1] = 0ULL; }

    const int tid = ty * 32 + tx;
    for (int cin0 = 0; cin0 < CIN; cin0 += 4) {
        for (int idx = tid; idx < 4 * 6 * 34; idx += 128) {
            int cc  = idx / 204;
            int rem = idx - cc * 204;
            int r   = rem / 34;
            int col = rem - r * 34;
            int gr = y0 + r - 1;
            int gc = x0 + col - 1;
            float v = 0.f;
            if (gr >= 0 && gr < Hh && gc >= 0 && gc < Ww)
                v = inb[(size_t)(cin0 + cc) * HWsz + gr * Ww + gc];
            s_in[cc][r][col] = v;
        }
        for (int idx = tid; idx < 288; idx += 128) {
            int pi  = idx / 36;
            int rem = idx - pi * 36;
            int cc  = rem / 9;
            int t   = rem - cc * 9;
            int oc0 = ocb + pi * 2;
            float w0 = w[((size_t)oc0 * CIN + cin0 + cc) * 9 + t];
            float w1 = w[((size_t)(oc0 + 1) * CIN + cin0 + cc) * 9 + t];
            s_w2[pi][cc][t] = make_float2(w0, w1);
        }
        __syncthreads();
#pragma unroll
        for (int cc = 0; cc < 4; cc++) {
            unsigned long long xx[6][3];
#pragma unroll
            for (int r = 0; r < 6; r++)
#pragma unroll
                for (int j = 0; j < 3; j++)
                    xx[r][j] = pk2(s_in[cc][r][tx + j]);
#pragma unroll
            for (int p = 0; p < 2; p++) {
                unsigned long long wv[9];
#pragma unroll
                for (int t = 0; t < 9; t++)
                    wv[t] = *(const unsigned long long*)&s_w2[ty * 2 + p][cc][t];
#pragma unroll
                for (int r = 0; r < 4; r++) {
#pragma unroll
                    for (int dy = 0; dy < 3; dy++) {
                        ffma2(acc2[r][p], xx[r + dy][0], wv[dy * 3 + 0]);
                        ffma2(acc2[r][p], xx[r + dy][1], wv[dy * 3 + 1]);
                        ffma2(acc2[r][p], xx[r + dy][2], wv[dy * 3 + 2]);
                    }
                }
            }
        }
        __syncthreads();
    }

#pragma unroll
    for (int p = 0; p < 2; p++) {
        int oclo = ocb + ty * 4 + 2 * p;
        float blo = bias ? bias[oclo]     : 0.f;
        float bhi = bias ? bias[oclo + 1] : 0.f;
#pragma unroll
        for (int r = 0; r < 4; r++) {
            float2 v = upk2(acc2[r][p]);
            float vx = fmaxf(v.x + blo, 0.f);
            float vy = fmaxf(v.y + bhi, 0.f);
            size_t base = (size_t)(y0 + r) * Ww + x0 + tx;
            out[(size_t)(b * Cout + oclo) * HWsz + base]     = vx;
            out[(size_t)(b * Cout + oclo + 1) * HWsz + base] = vy;
        }
    }
}

// ---------------- weight fp32 -> bf16 smem-mirror layout ----------------
__global__ void cvtw_k(const float* __restrict__ w, __nv_bfloat16* __restrict__ dst,
                       int Cout, int CIN)
{
    int idx = blockIdx.x * 256 + threadIdx.x;
    int total = Cout * CIN * 9;
    if (idx >= total) return;
    int ocg = idx / (CIN * 9);
    int rem = idx - ocg * (CIN * 9);
    int cin = rem / 9, tap = rem % 9;
    int ot = ocg >> 6, oc = ocg & 63;
    int kc = cin >> 5, c = cin & 31;
    dst[((((size_t)ot * (CIN / 32) + kc) * 9 + tap) * 64 + oc) * 40 + c] = __float2bfloat16(w[idx]);
}

// ---------------- x (fp32 NCHW b0) -> bf16 NHWC ----------------
__global__ void cvt_x_k(const float* __restrict__ x) {
    __shared__ float s[32][33];
    int p0 = blockIdx.x * 32;
    s[threadIdx.y][threadIdx.x] = x[(size_t)threadIdx.y * HWsz + p0 + threadIdx.x];
    __syncthreads();
    g_xh[(size_t)(p0 + threadIdx.y) * 32 + threadIdx.x] = __float2bfloat16(s[threadIdx.x][threadIdx.y]);
}

// ---------------- bf16 HMMA implicit-GEMM 3x3 conv (pad=1) ----------------
template<int CIN, bool POOL>
__global__ void __launch_bounds__(256) mmaconv_k(
    const __nv_bfloat16* __restrict__ in,
    const __nv_bfloat16* __restrict__ wbf,
    const float* __restrict__ bias,
    __nv_bfloat16* __restrict__ outNHWC,
    float* __restrict__ pool,
    int Cout)
{
    const int tid  = threadIdx.x;
    const int lane = tid & 31, warp = tid >> 5;
    const int x0 = blockIdx.x * 64;
    const int y  = blockIdx.y;
    const int ot = blockIdx.z;
    const int oc0 = ot * 64;
    const int m0 = (warp & 3) << 4;
    const int nb = (warp >> 2) << 5;

    __shared__ __align__(16) unsigned char smraw[15840 + 15360];
    char* sInB = (char*)smraw;
    char* sWB  = (char*)smraw + 15840;

    float acc[4][4];
#pragma unroll
    for (int nt = 0; nt < 4; nt++)
#pragma unroll
        for (int c = 0; c < 4; c++) acc[nt][c] = 0.f;

    const int KC = CIN / 32;
    for (int kc = 0; kc < KC; kc++) {
        __syncthreads();
        for (int idx = tid; idx < 792; idx += 256) {
            int dy = idx / 264; int r = idx - dy * 264;
            int px = r >> 2, cg = r & 3;
            int gy = y + dy - 1, gx = x0 - 1 + px;
            uint4 v = make_uint4(0u, 0u, 0u, 0u);
            if ((unsigned)gy < 384u && (unsigned)gx < 384u)
                v = *(const uint4*)(in + ((size_t)(gy * 384 + gx)) * CIN + kc * 32 + cg * 8);
            *(uint4*)(sInB + ((dy * 66 + px) * 40 + cg * 8) * 2) = v;
        }
        const uint4* wsrc = (const uint4*)(wbf + ((size_t)(ot * KC + kc) * 9) * 64 * 40);
#pragma unroll
        for (int tg = 0; tg < 3; tg++) {
            if (tg) __syncthreads();
            for (int idx = tid; idx < 960; idx += 256)
                ((uint4*)sWB)[idx] = wsrc[tg * 960 + idx];
            __syncthreads();
#pragma unroll
            for (int tt = 0; tt < 3; tt++) {
#pragma unroll
                for (int k16 = 0; k16 < 2; k16++) {
                    int aoff = (tt * 64 + m0 + (lane >> 2)) * 40 + k16 * 16 + (lane & 3) * 2;
                    uint32_t a0 = *(const uint32_t*)(sWB + aoff * 2);
                    uint32_t a1 = *(const uint32_t*)(sWB + (aoff + 8 * 40) * 2);
                    uint32_t a2 = *(const uint32_t*)(sWB + (aoff + 8) * 2);
                    uint32_t a3 = *(const uint32_t*)(sWB + (aoff + 8 * 40 + 8) * 2);
#pragma unroll
                    for (int nt = 0; nt < 4; nt++) {
                        int px = nb + nt * 8 + (lane >> 2) + tt;
                        int boff = (tg * 66 + px) * 40 + k16 * 16 + (lane & 3) * 2;
                        uint32_t b0 = *(const uint32_t*)(sInB + boff * 2);
                        uint32_t b1 = *(const uint32_t*)(sInB + (boff + 8) * 2);
                        asm volatile(
                            "mma.sync.aligned.m16n8k16.row.col.f32.bf16.bf16.f32 "
                            "{%0,%1,%2,%3},{%4,%5,%6,%7},{%8,%9},{%0,%1,%2,%3};\n"
                            : "+f"(acc[nt][0]), "+f"(acc[nt][1]),
                              "+f"(acc[nt][2]), "+f"(acc[nt][3])
                            : "r"(a0), "r"(a1), "r"(a2), "r"(a3), "r"(b0), "r"(b1));
                    }
                }
            }
        }
    }
    __syncthreads();

    float blo = __ldg(&bias[oc0 + m0 + (lane >> 2)]);
    float bhi = __ldg(&bias[oc0 + m0 + (lane >> 2) + 8]);

    if (POOL) {
        float slo = 0.f, shi = 0.f;
#pragma unroll
        for (int nt = 0; nt < 4; nt++) {
            slo += fmaxf(acc[nt][0] + blo, 0.f) + fmaxf(acc[nt][1] + blo, 0.f);
            shi += fmaxf(acc[nt][2] + bhi, 0.f) + fmaxf(acc[nt][3] + bhi, 0.f);
        }
        slo += __shfl_xor_sync(0xffffffffu, slo, 1);
        slo += __shfl_xor_sync(0xffffffffu, slo, 2);
        shi += __shfl_xor_sync(0xffffffffu, shi, 1);
        shi += __shfl_xor_sync(0xffffffffu, shi, 2);
        if ((lane & 3) == 0) {
            atomicAdd(&pool[oc0 + m0 + (lane >> 2)], slo);
            atomicAdd(&pool[oc0 + m0 + (lane >> 2) + 8], shi);
        }
    } else {
        __nv_bfloat16* sOut = (__nv_bfloat16*)smraw;
#pragma unroll
        for (int nt = 0; nt < 4; nt++) {
            int px = nb + nt * 8 + (lane & 3) * 2;
            int oc = m0 + (lane >> 2);
            sOut[px * 64 + oc]           = __float2bfloat16(fmaxf(acc[nt][0] + blo, 0.f));
            sOut[(px + 1) * 64 + oc]     = __float2bfloat16(fmaxf(acc[nt][1] + blo, 0.f));
            sOut[px * 64 + oc + 8]       = __float2bfloat16(fmaxf(acc[nt][2] + bhi, 0.f));
            sOut[(px + 1) * 64 + oc + 8] = __float2bfloat16(fmaxf(acc[nt][3] + bhi, 0.f));
        }
        __syncthreads();
        for (int idx = tid; idx < 512; idx += 256) {
            int px = idx >> 3, og = idx & 7;
            *(uint4*)(outNHWC + ((size_t)(y * 384 + x0 + px)) * Cout + oc0 + og * 8) =
                *(const uint4*)(sOut + px * 64 + og * 8);
        }
    }
}

// ---------------- zero scratch scalars ----------------
__global__ void zero_k() {
    int t = threadIdx.x;
    if (t < 256) { g_pool[t] = 0.f; g_ssq[t] = 0.f; }
    if (t < 512) g_S[t] = 0.f;
}

// ---------------- logits + argmax ----------------
__global__ void logits_k(const float* __restrict__ fcw, const float* __restrict__ fcb) {
    __shared__ float l[3];
    int t = threadIdx.x;
    if (t < 3) {
        float s = 0.f;
        const float inv = 1.0f / (float)HWsz;
        for (int k = 0; k < 256; k++)
            s = fmaf(fcw[t * 256 + k], g_pool[k] * inv, s);
        l[t] = s + fcb[t];
    }
    __syncthreads();
    if (t == 0) {
        int best = 0; float bv = l[0];
        if (l[1] > bv) { bv = l[1]; best = 1; }
        if (l[2] > bv) { bv = l[2]; best = 2; }
        g_sel[0] = best;
    }
}

// ---------------- rgb branch copy ----------------
__global__ void copy_rgb_k(const float* __restrict__ x) {
    if (__ldg(g_sel) != 0) return;
    size_t i = (size_t)blockIdx.x * blockDim.x + threadIdx.x;
    const float4* src = (const float4*)x;
    float4* dst = (float4*)g_xb;
    size_t n4 = (size_t)NB * 32 * HWsz / 4;
    if (i < n4) dst[i] = src[i];
}

// ---------------- fused LayerNorm + 1x1 pwconv (32 -> 96) ----------------
__global__ void __launch_bounds__(128) ln_pw_k(
    const float* __restrict__ lnw, const float* __restrict__ lnb,
    const float* __restrict__ pww)
{
    __shared__ float s_w[96 * 32];
    __shared__ float s_lw[32], s_lb[32];
    int tid = threadIdx.x;
    for (int i = tid; i < 96 * 32; i += 128) s_w[i] = pww[i];
    if (tid < 32) { s_lw[tid] = lnw[tid]; s_lb[tid] = lnb[tid]; }
    __syncthreads();

    size_t pair = (size_t)blockIdx.x * 128 + tid;
    size_t gp = pair * 2;
    int b = (int)(gp / HWsz);
    int p = (int)(gp % HWsz);

    float a0[32], a1[32];
    float m0 = 0.f, m1 = 0.f;
#pragma unroll
    for (int c = 0; c < 32; c++) {
        float2 v = *(const float2*)&g_xb[(size_t)(b * 32 + c) * HWsz + p];
        a0[c] = v.x; a1[c] = v.y;
        m0 += v.x; m1 += v.y;
    }
    m0 *= (1.f / 32.f); m1 *= (1.f / 32.f);
    float v0 = 0.f, v1 = 0.f;
#pragma unroll
    for (int c = 0; c < 32; c++) {
        float d0 = a0[c] - m0, d1 = a1[c] - m1;
        v0 = fmaf(d0, d0, v0); v1 = fmaf(d1, d1, v1);
    }
    float r0 = rsqrtf(v0 * (1.f / 32.f) + 1e-6f);
    float r1 = rsqrtf(v1 * (1.f / 32.f) + 1e-6f);
#pragma unroll
    for (int c = 0; c < 32; c++) {
        a0[c] = fmaf((a0[c] - m0) * r0, s_lw[c], s_lb[c]);
        a1[c] = fmaf((a1[c] - m1) * r1, s_lw[c], s_lb[c]);
    }
    for (int oc = 0; oc < 96; oc++) {
        float acc0 = 0.f, acc1 = 0.f;
#pragma unroll
        for (int c = 0; c < 32; c++) {
            float w = s_w[oc * 32 + c];
            acc0 = fmaf(w, a0[c], acc0);
            acc1 = fmaf(w, a1[c], acc1);
        }
        float2 o; o.x = acc0; o.y = acc1;
        *(float2*)&g_qkv_pre[(size_t)(b * 96 + oc) * HWsz + p] = o;
    }
}

// ---------------- depthwise 3x3, 4 px/thread, optional gelu ----------------
__global__ void dw4_k(const float* __restrict__ in, const float* __restrict__ w,
                      float* __restrict__ out, int Cn, int doGelu, int totalQuads)
{
    int idx = blockIdx.x * 256 + threadIdx.x;
    if (idx >= totalQuads) return;
    int plane = idx / 36864;
    int q = idx - plane * 36864;
    int y = q / 96, qx = q - y * 96;
    int x0 = qx * 4;
    int c = plane % Cn;
    const float* ip = in + (size_t)plane * HWsz;
    const float* wp = w + c * 9;
    float wr[9];
#pragma unroll
    for (int t = 0; t < 9; t++) wr[t] = __ldg(&wp[t]);
    float o[4] = {0.f, 0.f, 0.f, 0.f};
    if (y >= 1 && y <= 382 && qx >= 1 && qx <= 94) {
#pragma unroll
        for (int dy = 0; dy < 3; dy++) {
            const float* row = ip + (size_t)(y + dy - 1) * Ww + x0;
            float l = row[-1];
            float4 m = *(const float4*)row;
            float rr = row[4];
            float w0 = wr[dy * 3], w1 = wr[dy * 3 + 1], w2 = wr[dy * 3 + 2];
            o[0] = fmaf(w0, l,   fmaf(w1, m.x, fmaf(w2, m.y, o[0])));
            o[1] = fmaf(w0, m.x, fmaf(w1, m.y, fmaf(w2, m.z, o[1])));
            o[2] = fmaf(w0, m.y, fmaf(w1, m.z, fmaf(w2, m.w, o[2])));
            o[3] = fmaf(w0, m.z, fmaf(w1, m.w, fmaf(w2, rr,  o[3])));
        }
    } else {
#pragma unroll
        for (int j = 0; j < 4; j++) {
            int x = x0 + j;
            float s = 0.f;
#pragma unroll
            for (int dy = 0; dy < 3; dy++) {
                int yy = y + dy - 1;
                if (yy < 0 || yy >= Hh) continue;
#pragma unroll
                for (int dx = 0; dx < 3; dx++) {
                    int xx = x + dx - 1;
                    if (xx < 0 || xx >= Ww) continue;
                    s = fmaf(wr[dy * 3 + dx], ip[(size_t)yy * Ww + xx], s);
                }
            }
            o[j] = s;
        }
    }
    if (doGelu) {
#pragma unroll
        for (int j = 0; j < 4; j++) o[j] = gelu_exact(o[j]);
    }
    *(float4*)(out + (size_t)plane * HWsz + (size_t)y * Ww + x0) = make_float4(o[0], o[1], o[2], o[3]);
}

// ---------------- fused sumsq + gram, atomic accumulate ----------------
__global__ void __launch_bounds__(256) sg_k() {
    int bid = blockIdx.x;
    int chunk = bid & 15, h = (bid >> 4) & 7, b = bid >> 7;
    const float* qp = g_qkv + (size_t)(b * 96 + h * 4) * HWsz;
    const float* kp = g_qkv + (size_t)(b * 96 + 32 + h * 4) * HWsz;
    float acc[24];
#pragma unroll
    for (int v = 0; v < 24; v++) acc[v] = 0.f;
    int i0 = chunk * 9216;
    for (int i = i0 + threadIdx.x; i < i0 + 9216; i += 256) {
        float qv[4], kv[4];
#pragma unroll
        for (int c = 0; c < 4; c++) {
            qv[c] = qp[(size_t)c * HWsz + i];
            kv[c] = kp[(size_t)c * HWsz + i];
        }
#pragma unroll
        for (int c = 0; c < 4; c++) {
            acc[16 + c] = fmaf(qv[c], qv[c], acc[16 + c]);
            acc[20 + c] = fmaf(kv[c], kv[c], acc[20 + c]);
#pragma unroll
            for (int d = 0; d < 4; d++)
                acc[c * 4 + d] = fmaf(qv[c], kv[d], acc[c * 4 + d]);
        }
    }
#pragma unroll
    for (int v = 0; v < 24; v++)
#pragma unroll
        for (int off = 16; off; off >>= 1)
            acc[v] += __shfl_down_sync(0xffffffffu, acc[v], off);
    __shared__ float sh[8][24];
    int warp = threadIdx.x >> 5, lane = threadIdx.x & 31;
    if (lane == 0)
#pragma unroll
        for (int v = 0; v < 24; v++) sh[warp][v] = acc[v];
    __syncthreads();
    if (threadIdx.x < 24) {
        float s = 0.f;
#pragma unroll
        for (int wq = 0; wq < 8; wq++) s += sh[wq][threadIdx.x];
        int v = threadIdx.x;
        if (v < 16)      atomicAdd(&g_S[(b * 8 + h) * 16 + v], s);
        else if (v < 20) atomicAdd(&g_ssq[b * 32 + h * 4 + (v - 16)], s);
        else             atomicAdd(&g_ssq[128 + b * 32 + h * 4 + (v - 20)], s);
    }
}

// ---------------- normalize + temperature + softmax ----------------
__global__ void attn_k(const float* __restrict__ temp) {
    int t = threadIdx.x;
    if (t >= 32) return;
    int b = t >> 3, h = t & 7;
    float nq[4], nk[4];
#pragma unroll
    for (int c = 0; c < 4; c++) {
        nq[c] = fmaxf(sqrtf(g_ssq[b * 32 + h * 4 + c]), 1e-12f);
        nk[c] = fmaxf(sqrtf(g_ssq[128 + b * 32 + h * 4 + c]), 1e-12f);
    }
    float tp = temp[h];
    float A[16];
#pragma unroll
    for (int c = 0; c < 4; c++)
#pragma unroll
        for (int d = 0; d < 4; d++)
            A[c * 4 + d] = g_S[(b * 8 + h) * 16 + c * 4 + d] / (nq[c] * nk[d]) * tp;
#pragma unroll
    for (int c = 0; c < 4; c++) {
        float m = A[c * 4];
#pragma unroll
        for (int d = 1; d < 4; d++) m = fmaxf(m, A[c * 4 + d]);
        float sum = 0.f;
#pragma unroll
        for (int d = 0; d < 4; d++) { A[c * 4 + d] = expf(A[c * 4 + d] - m); sum += A[c * 4 + d]; }
        float inv = 1.f / sum;
#pragma unroll
        for (int d = 0; d < 4; d++) g_attn[(b * 8 + h) * 16 + c * 4 + d] = A[c * 4 + d] * inv;
    }
}

// ---------------- fused: attn@v -> proj -> +xb -> ff1 -> gelu ----------------
__global__ void __launch_bounds__(128) outproj_k(
    const float* __restrict__ projw, const float* __restrict__ ff1w)
{
    __shared__ float s_at[128], s_pw[1024], s_fw[1024];
    int b = blockIdx.z;
    int tid = threadIdx.x;
    for (int i = tid; i < 1024; i += 128) { s_pw[i] = projw[i]; s_fw[i] = ff1w[i]; }
    if (tid < 128) s_at[tid] = g_attn[b * 128 + tid];
    __syncthreads();

    int p = blockIdx.x * 128 + tid;
    float v[32];
#pragma unroll
    for (int c = 0; c < 32; c++)
        v[c] = g_qkv[(size_t)(b * 96 + 64 + c) * HWsz + p];
    float o[32];
#pragma unroll
    for (int c = 0; c < 32; c++) {
        int h = c >> 2, ci = c & 3;
        const float* at = &s_at[h * 16 + ci * 4];
        int vb = c & ~3;
        o[c] = at[0] * v[vb] + at[1] * v[vb + 1] + at[2] * v[vb + 2] + at[3] * v[vb + 3];
    }
    float y[32];
#pragma unroll
    for (int c = 0; c < 32; c++) {
        float acc = g_xb[(size_t)(b * 32 + c) * HWsz + p];
#pragma unroll
        for (int c2 = 0; c2 < 32; c2++)
            acc = fmaf(s_pw[c * 32 + c2], o[c2], acc);
        y[c] = acc;
    }
#pragma unroll
    for (int c = 0; c < 32; c++) {
        float acc = 0.f;
#pragma unroll
        for (int c2 = 0; c2 < 32; c2++)
            acc = fmaf(s_fw[c * 32 + c2], y[c2], acc);
        g_ff[(size_t)(b * 32 + c) * HWsz + p] = gelu_exact(acc);
    }
}

// ---------------- launch ----------------
extern "C" void kernel_launch(void* const* d_in, const int* in_sizes, int n_in,
                              void* d_out, int out_size)
{
    const float* x       = (const float*)d_in[0];
    const float* ln_w    = (const float*)d_in[1];
    const float* ln_b    = (const float*)d_in[2];
    const float* temper  = (const float*)d_in[3];
    const float* pw_w    = (const float*)d_in[4];
    const float* dw_w    = (const float*)d_in[5];
    const float* proj_w  = (const float*)d_in[6];
    const float* ff1_w   = (const float*)d_in[7];
    const float* ffdw_w  = (const float*)d_in[8];
    const float* det_w1  = (const float*)d_in[9];
    const float* det_b1  = (const float*)d_in[10];
    const float* det_w2  = (const float*)d_in[11];
    const float* det_b2  = (const float*)d_in[12];
    const float* det_w3  = (const float*)d_in[13];
    const float* det_b3  = (const float*)d_in[14];
    const float* det_fcw = (const float*)d_in[15];
    const float* det_fcb = (const float*)d_in[16];
    const float* hvi_w1  = (const float*)d_in[17];
    const float* hvi_b1  = (const float*)d_in[18];
    const float* hvi_w2  = (const float*)d_in[19];
    const float* hvi_b2  = (const float*)d_in[20];
    const float* ycc_w1  = (const float*)d_in[21];
    const float* ycc_b1  = (const float*)d_in[22];
    const float* ycc_w2  = (const float*)d_in[23];
    const float* ycc_b2  = (const float*)d_in[24];
    float* outp = (float*)d_out;

    float *p_det1, *p_pool, *p_xb, *p_qkv_pre, *p_qkv, *p_ff;
    int* p_sel;
    __nv_bfloat16 *p_xh, *p_det1h, *p_det2h, *p_wbf1, *p_wbf2, *p_wbf3;
    cudaGetSymbolAddress((void**)&p_det1, g_det1);
    cudaGetSymbolAddress((void**)&p_pool, g_pool);
    cudaGetSymbolAddress((void**)&p_sel,  g_sel);
    cudaGetSymbolAddress((void**)&p_xb,   g_xb);
    cudaGetSymbolAddress((void**)&p_qkv_pre, g_qkv_pre);
    cudaGetSymbolAddress((void**)&p_qkv,  g_qkv);
    cudaGetSymbolAddress((void**)&p_ff,   g_ff);
    cudaGetSymbolAddress((void**)&p_xh,   g_xh);
    cudaGetSymbolAddress((void**)&p_det1h, g_det1h);
    cudaGetSymbolAddress((void**)&p_det2h, g_det2h);
    cudaGetSymbolAddress((void**)&p_wbf1, g_wbf1);
    cudaGetSymbolAddress((void**)&p_wbf2, g_wbf2);
    cudaGetSymbolAddress((void**)&p_wbf3, g_wbf3);

    dim3 blk(32, 4);

    // weight conversions + zeroing + x->NHWC bf16
    cvtw_k<<<(64 * 32 * 9 + 255) / 256, 256>>>(det_w1, p_wbf1, 64, 32);
    cvtw_k<<<(128 * 64 * 9 + 255) / 256, 256>>>(det_w2, p_wbf2, 128, 64);
    cvtw_k<<<(256 * 128 * 9 + 255) / 256, 256>>>(det_w3, p_wbf3, 256, 128);
    zero_k<<<1, 1024>>>();
    cvt_x_k<<<HWsz / 32, dim3(32, 32)>>>(x);

    // detector (batch 0, all bf16 HMMA)
    mmaconv_k<32,  false><<<dim3(6, 384, 1), 256>>>(p_xh,    p_wbf1, det_b1, p_det1h, nullptr, 64);
    mmaconv_k<64,  false><<<dim3(6, 384, 2), 256>>>(p_det1h, p_wbf2, det_b2, p_det2h, nullptr, 128);
    mmaconv_k<128, true ><<<dim3(6, 384, 4), 256>>>(p_det2h, p_wbf3, det_b3, nullptr, p_pool, 256);
    logits_k<<<1, 32>>>(det_fcw, det_fcb);

    // branch (fp32, packed f32x2 FMA; predicated on g_sel)
    copy_rgb_k<<<(NB * 32 * HWsz / 4 + 1023) / 1024, 1024>>>(x);
    conv3x3_p2_k<32><<<dim3(12, 96, 16), blk>>>(x,      hvi_w1, hvi_b1, p_det1, 64, p_sel, 1);
    conv3x3_p2_k<64><<<dim3(12, 96, 8),  blk>>>(p_det1, hvi_w2, hvi_b2, p_xb,   32, p_sel, 1);
    conv3x3_p2_k<32><<<dim3(12, 96, 16), blk>>>(x,      ycc_w1, ycc_b1, p_det1, 64, p_sel, 2);
    conv3x3_p2_k<64><<<dim3(12, 96, 8),  blk>>>(p_det1, ycc_w2, ycc_b2, p_xb,   32, p_sel, 2);

    // LN + pw 1x1
    ln_pw_k<<<(NB * HWsz / 2) / 128, 128>>>(ln_w, ln_b, pw_w);
    // depthwise 3x3 (96 ch)
    dw4_k<<<(NB * 96 * 36864 + 255) / 256, 256>>>(p_qkv_pre, dw_w, p_qkv, 96, 0, NB * 96 * 36864);
    // fused sumsq + gram
    sg_k<<<512, 256>>>();
    attn_k<<<1, 32>>>(temper);
    // attn apply + proj + residual + ff1 + gelu
    outproj_k<<<dim3(HWsz / 128, 1, NB), 128>>>(proj_w, ff1_w);
    // ffdw depthwise + gelu -> out
    dw4_k<<<(NB * 32 * 36864 + 255) / 256, 256>>>(p_ff, ffdw_w, outp, 32, 1, NB * 32 * 36864);

    (void)in_sizes; (void)n_in; (void)out_size;
}